// round 13
// baseline (speedup 1.0000x reference)
#include <cuda_runtime.h>
#include <math.h>

#define BB 16
#define LATD 8
#define NPTS 500000
#define XSZ 256
#define HSPEC 129   // XSZ/2 + 1
#define IMG_ELEMS (BB*XSZ*XSZ)

// ---------------- scratch (device globals; no allocation allowed) ----------
__device__ float  g_img[IMG_ELEMS];                  // 4 MB accumulation image
__device__ float2 g_spec[BB*XSZ*HSPEC];              // spectrum, layout [b][y][k]
__device__ float  g_params[BB][16];                  // R rows(6), shifts(2), h(8)
__device__ float2 g_tw[128];                         // exp(-2*pi*i*k/256)

// Gaussian kernel (sigma=1, radius=3), normalized (double-derived constants)
__device__ __constant__ float c_gk[7] = {
    0.0044330481f, 0.0540055826f, 0.2420362294f, 0.3990502730f,
    0.2420362294f, 0.0540055826f, 0.0044330481f
};

#define SKEW(i) ((i) + ((i) >> 5))   // bank-conflict skew for SoA smem

// ---------------- zero + prep (merged) --------------------------------------

__global__ void zero_prep_kernel(const float* __restrict__ rows,
                                 const float* __restrict__ shifts,
                                 const float* __restrict__ latent,
                                 const float* __restrict__ W0, const float* __restrict__ b0,
                                 const float* __restrict__ W1, const float* __restrict__ b1,
                                 const float* __restrict__ W2, const float* __restrict__ b2,
                                 const float* __restrict__ W3, const float* __restrict__ b3) {
    int i = blockIdx.x * blockDim.x + threadIdx.x;
    ((float4*)g_img)[i] = make_float4(0.f, 0.f, 0.f, 0.f);
    if (blockIdx.x != 0) return;
    int tid = threadIdx.x;
    if (tid < 128) {
        double s, c;
        sincos(-3.14159265358979323846 * (double)tid / 128.0, &s, &c);
        g_tw[tid] = make_float2((float)c, (float)s);
    }
    int b = tid;
    if (b >= BB) return;
    // ---- FROZEN position-path arithmetic (do not modify) ----
    float rot  = rows[b*3+0];
    float tilt = rows[b*3+1];
    float psi  = rows[b*3+2];
    float ca = cosf(rot),  sa = sinf(rot);
    float cb = cosf(tilt), sb = sinf(tilt);
    float cg = cosf(psi),  sg = sinf(psi);
    float cgcb = __fmul_rn(cg, cb);
    float sgcb = __fmul_rn(sg, cb);
    g_params[b][0] = __fsub_rn(__fmul_rn(cgcb, ca), __fmul_rn(sg, sa));
    g_params[b][1] = __fadd_rn(__fmul_rn(cgcb, sa), __fmul_rn(sg, ca));
    g_params[b][2] = -__fmul_rn(cg, sb);
    g_params[b][3] = __fsub_rn(__fmul_rn(-sgcb, ca), __fmul_rn(cg, sa));
    g_params[b][4] = __fadd_rn(__fmul_rn(-sgcb, sa), __fmul_rn(cg, ca));
    g_params[b][5] = __fmul_rn(sg, sb);
    g_params[b][6] = shifts[b*2+0];
    g_params[b][7] = shifts[b*2+1];

    float h[LATD];
    #pragma unroll
    for (int j = 0; j < LATD; j++) {
        float z = b0[j];
        #pragma unroll
        for (int l = 0; l < LATD; l++) z += latent[b*LATD+l] * W0[l*LATD+j];
        h[j] = sinf(30.0f * z);
    }
    const float* Ws[3] = {W1, W2, W3};
    const float* bs[3] = {b1, b2, b3};
    for (int L = 0; L < 3; L++) {
        float t[LATD];
        #pragma unroll
        for (int j = 0; j < LATD; j++) {
            float z = bs[L][j];
            #pragma unroll
            for (int l = 0; l < LATD; l++) z += h[l] * Ws[L][l*LATD+j];
            t[j] = sinf(z);
        }
        #pragma unroll
        for (int j = 0; j < LATD; j++) h[j] += t[j];
    }
    #pragma unroll
    for (int j = 0; j < LATD; j++) g_params[b][8+j] = h[j];
}

// ---------------- scatter ----------------------------------------------------

__global__ void scatter_kernel(const float* __restrict__ coords,
                               const float* __restrict__ values,
                               const float* __restrict__ Wd,
                               const float* __restrict__ bd) {
    __shared__ float sp[BB][16];
    __shared__ float sc[768];
    int t = threadIdx.x;
    if (t < BB*16) ((float*)sp)[t] = ((const float*)g_params)[t];
    int base = blockIdx.x * 256 * 3;
    #pragma unroll
    for (int f = 0; f < 3; f++) {
        int g = base + t + f*256;
        sc[t + f*256] = (g < NPTS*3) ? coords[g] : 0.0f;
    }
    __syncthreads();

    int n = blockIdx.x * blockDim.x + t;
    if (n >= NPTS) return;

    float cx = sc[t*3+0];
    float cy = sc[t*3+1];
    float cz = sc[t*3+2];
    float v   = values[n];
    float bdn = bd[n];
    float wd[LATD];
    #pragma unroll
    for (int l = 0; l < LATD; l++) wd[l] = Wd[l*NPTS + n];

    #pragma unroll
    for (int b = 0; b < BB; b++) {
        // ---- FROZEN position-path arithmetic (do not modify) ----
        float x = __fmul_rn(sp[b][0], cx);
        x = __fmaf_rn(sp[b][1], cy, x);
        x = __fmaf_rn(sp[b][2], cz, x);
        float y = __fmul_rn(sp[b][3], cx);
        y = __fmaf_rn(sp[b][4], cy, y);
        y = __fmaf_rn(sp[b][5], cz, y);
        float fx = rintf(__fadd_rn(__fadd_rn(x, sp[b][6]), 128.0f));
        float fy = rintf(__fadd_rn(__fadd_rn(y, sp[b][7]), 128.0f));
        fx = fminf(fmaxf(fx, 0.0f), 255.0f);
        fy = fminf(fmaxf(fy, 0.0f), 255.0f);
        int ix = (int)fx;
        int iy = (int)fy;
        float dot = sp[b][8] * wd[0];
        #pragma unroll
        for (int l = 1; l < LATD; l++) dot += sp[b][8+l] * wd[l];
        float val = v + (dot + bdn);
        atomicAdd(&g_img[(b << 16) | (iy << 8) | ix], val);
    }
}

// ---- radix-4 Stockham FFT, N=256, 64 lanes per FFT, SoA smem + skew --------
// (used by fftrow / ifftrow — the measured-best row-kernel configuration)

template<bool INV>
__device__ __forceinline__ void fft_r4(float* RA, float* IA, float* RB, float* IB,
                                       const float2* tw, int lane) {
    float* sr = RA; float* si = IA; float* dr = RB; float* di = IB;
    #pragma unroll
    for (int st = 0; st < 4; st++) {
        const int Ns = 1 << (2*st);
        int k    = lane & (Ns - 1);
        int base = ((lane - k) << 2) + k;
        float2 w1 = tw[k << (6 - 2*st)];
        if (INV) w1.y = -w1.y;
        float w2r = w1.x*w1.x - w1.y*w1.y, w2i = 2.f*w1.x*w1.y;
        float w3r = w2r*w1.x - w2i*w1.y,  w3i = w2r*w1.y + w2i*w1.x;
        float ar  = sr[SKEW(lane)],       ai  = si[SKEW(lane)];
        float br_ = sr[SKEW(lane+64)],    bi  = si[SKEW(lane+64)];
        float cr  = sr[SKEW(lane+128)],   ci  = si[SKEW(lane+128)];
        float dr_ = sr[SKEW(lane+192)],   di_ = si[SKEW(lane+192)];
        float tbr = w1.x*br_ - w1.y*bi,   tbi = w1.x*bi  + w1.y*br_;
        float tcr = w2r*cr  - w2i*ci,     tci = w2r*ci  + w2i*cr;
        float tdr = w3r*dr_ - w3i*di_,    tdi = w3r*di_ + w3i*dr_;
        float t0r = ar + tcr,  t0i = ai + tci;
        float t1r = ar - tcr,  t1i = ai - tci;
        float t2r = tbr + tdr, t2i = tbi + tdi;
        float t3r = tbr - tdr, t3i = tbi - tdi;
        dr[SKEW(base)]      = t0r + t2r;  di[SKEW(base)]      = t0i + t2i;
        dr[SKEW(base+2*Ns)] = t0r - t2r;  di[SKEW(base+2*Ns)] = t0i - t2i;
        if (!INV) {
            dr[SKEW(base+Ns)]   = t1r + t3i;  di[SKEW(base+Ns)]   = t1i - t3r;
            dr[SKEW(base+3*Ns)] = t1r - t3i;  di[SKEW(base+3*Ns)] = t1i + t3r;
        } else {
            dr[SKEW(base+Ns)]   = t1r - t3i;  di[SKEW(base+Ns)]   = t1i + t3r;
            dr[SKEW(base+3*Ns)] = t1r + t3i;  di[SKEW(base+3*Ns)] = t1i - t3r;
        }
        __syncthreads();
        float* tp;
        tp = sr; sr = dr; dr = tp;
        tp = si; si = di; di = tp;
    }
}

// fused y-blur + x-blur + two-for-one forward row rFFT (measured 12.0us).
// Block: 256 threads = 4 FFTs = 4 row pairs; grid 512. Writes [b][y][k].
__global__ void fftrow_kernel() {
    __shared__ float RA[4][264], IA[4][264], RB[4][264], IB[4][264];
    __shared__ float2 tw[64];
    int tid = threadIdx.x, sub = tid >> 6, lane = tid & 63;
    if (tid < 64) tw[tid] = g_tw[tid];
    int rp = blockIdx.x * 4 + sub;        // pair index, 128 pairs per image
    int b  = rp >> 7;
    int y0 = (rp & 127) << 1;
    int y1 = y0 + 1;
    const float* imgb = g_img + (b << 16);
    for (int i = lane; i < XSZ; i += 64) {
        float a0 = 0.f, a1 = 0.f;
        #pragma unroll
        for (int d = -3; d <= 3; d++) {
            int ya = y0 + d;
            if (ya >= 0 && ya < XSZ) a0 += c_gk[d+3] * imgb[(ya << 8) + i];
            int yb = y1 + d;
            if (yb >= 0 && yb < XSZ) a1 += c_gk[d+3] * imgb[(yb << 8) + i];
        }
        RB[sub][i] = a0;
        IB[sub][i] = a1;
    }
    __syncthreads();
    for (int i = lane; i < XSZ; i += 64) {
        float a0 = 0.f, a1 = 0.f;
        #pragma unroll
        for (int d = -3; d <= 3; d++) {
            int xx = i + d;
            if (xx >= 0 && xx < XSZ) {
                a0 += c_gk[d+3] * RB[sub][xx];
                a1 += c_gk[d+3] * IB[sub][xx];
            }
        }
        RA[sub][SKEW(i)] = a0;
        IA[sub][SKEW(i)] = a1;
    }
    __syncthreads();
    fft_r4<false>(RA[sub], IA[sub], RB[sub], IB[sub], tw, lane);
    long base0 = (long)((b << 8) | y0) * HSPEC;
    long base1 = (long)((b << 8) | y1) * HSPEC;
    for (int k = lane; k <= 128; k += 64) {
        int kn = (256 - k) & 255;
        float zr = RA[sub][SKEW(k)],  zi = IA[sub][SKEW(k)];
        float nr = RA[sub][SKEW(kn)], ni = IA[sub][SKEW(kn)];
        g_spec[base0 + k] = make_float2(0.5f*(zr + nr), 0.5f*(zi - ni));
        g_spec[base1 + k] = make_float2(0.5f*(zi + ni), 0.5f*(nr - zr));
    }
}

// ---- FFT256 as 16x16 in registers with SHUFFLE transpose (for fftcol) ------

#define C16_1 0.92387953251128674f
#define S16_1 0.38268343236508978f
#define C16_2 0.70710678118654752f

__device__ __forceinline__ float2 cmulc(float2 a, float wx, float wy) {
    return make_float2(a.x*wx - a.y*wy, a.x*wy + a.y*wx);
}

template<bool INV>
__device__ __forceinline__ void bfly4(float2& a, float2& b, float2& c, float2& d) {
    float t0x=a.x+c.x, t0y=a.y+c.y;
    float t1x=a.x-c.x, t1y=a.y-c.y;
    float t2x=b.x+d.x, t2y=b.y+d.y;
    float t3x=b.x-d.x, t3y=b.y-d.y;
    a = make_float2(t0x+t2x, t0y+t2y);
    c = make_float2(t0x-t2x, t0y-t2y);
    if (!INV) { b = make_float2(t1x+t3y, t1y-t3x); d = make_float2(t1x-t3y, t1y+t3x); }
    else      { b = make_float2(t1x-t3y, t1y+t3x); d = make_float2(t1x+t3y, t1y-t3x); }
}

template<bool INV>
__device__ __forceinline__ void fft16(float2 v[16]) {
    const float sg = INV ? 1.0f : -1.0f;
    bfly4<INV>(v[0], v[4], v[8],  v[12]);
    bfly4<INV>(v[1], v[5], v[9],  v[13]);
    bfly4<INV>(v[2], v[6], v[10], v[14]);
    bfly4<INV>(v[3], v[7], v[11], v[15]);
    v[5]  = cmulc(v[5],  C16_1,  sg*S16_1);
    v[9]  = cmulc(v[9],  C16_2,  sg*C16_2);
    v[6]  = cmulc(v[6],  C16_2,  sg*C16_2);
    v[13] = cmulc(v[13], S16_1,  sg*C16_1);
    v[7]  = cmulc(v[7],  S16_1,  sg*C16_1);
    v[10] = INV ? make_float2(-v[10].y, v[10].x)
                : make_float2( v[10].y, -v[10].x);
    v[14] = cmulc(v[14], -C16_2,  sg*C16_2);
    v[11] = cmulc(v[11], -C16_2,  sg*C16_2);
    v[15] = cmulc(v[15], -C16_1, -sg*S16_1);
    bfly4<INV>(v[0],  v[1],  v[2],  v[3]);
    bfly4<INV>(v[4],  v[5],  v[6],  v[7]);
    bfly4<INV>(v[8],  v[9],  v[10], v[11]);
    bfly4<INV>(v[12], v[13], v[14], v[15]);
}

#define SLOT(k) ((((k) & 3) << 2) | ((k) >> 2))

// in-place SLOT permutation (SLOT is an involution; fixed pts 0,5,10,15)
__device__ __forceinline__ void slot_permute(float2 v[16]) {
    float2 tmp;
    tmp = v[1];  v[1]  = v[4];  v[4]  = tmp;
    tmp = v[2];  v[2]  = v[8];  v[8]  = tmp;
    tmp = v[3];  v[3]  = v[12]; v[12] = tmp;
    tmp = v[6];  v[6]  = v[9];  v[9]  = tmp;
    tmp = v[7];  v[7]  = v[13]; v[13] = tmp;
    tmp = v[11]; v[11] = v[14]; v[14] = tmp;
}

// 16x16 register transpose across a 16-lane group via shfl_xor (no barriers).
__device__ __forceinline__ void shfl_transpose16(float2 v[16], int lane16) {
    #pragma unroll
    for (int s = 0; s < 4; s++) {
        const int m = 1 << s;
        bool hi = (lane16 & m) != 0;
        #pragma unroll
        for (int base = 0; base < 16; base++) {
            if (base & m) continue;
            const int lo = base, hx = base | m;
            float2 send = hi ? v[lo] : v[hx];
            float2 recv;
            recv.x = __shfl_xor_sync(0xFFFFFFFFu, send.x, m, 16);
            recv.y = __shfl_xor_sync(0xFFFFFFFFu, send.y, m, 16);
            if (hi) v[lo] = recv; else v[hx] = recv;
        }
    }
}

// FFT256 with zero-barrier transpose. Input v[n2] = x[t + 16 n2].
// Output: X[t + 16 k1] at v[SLOT(k1)].
template<bool INV>
__device__ __forceinline__ void fft256_shfl(float2 v[16], int t,
                                            const float2* stw) {
    fft16<INV>(v);
    slot_permute(v);                      // v[k2] = y[t][k2]
    #pragma unroll
    for (int k2 = 0; k2 < 16; k2++) {     // twiddle W256^(t*k2), conj if INV
        int e = t * k2;
        float2 w = stw[e & 127];
        if (e & 128) { w.x = -w.x; w.y = -w.y; }
        if (INV) w.y = -w.y;
        float2 a = v[k2];
        v[k2] = make_float2(a.x*w.x - a.y*w.y, a.x*w.y + a.y*w.x);
    }
    shfl_transpose16(v, t);               // v[n1] = M[n1][t]
    fft16<INV>(v);
}

// forward y FFT, ctf multiply, inverse y FFT — register FFT, shuffle
// transposes, 2 barriers total. Block: 128 threads = 8 k-columns; grid BB*17.
__global__ void __launch_bounds__(128) fftcol_kernel(const float* __restrict__ ctf) {
    __shared__ float2 tin[XSZ][9];        // 18 KB   in/out tile (padded)
    __shared__ float  ctile[XSZ][9];      // 9.2 KB  ctf tile
    __shared__ float2 stw[128];           // 1 KB
    int tid = threadIdx.x;
    int f = tid >> 4, t = tid & 15;
    stw[tid] = g_tw[tid];
    int b   = blockIdx.x / 17;
    int kx0 = (blockIdx.x % 17) * 8;
    // stage input spectrum + ctf tile (coalesced 64B/32B chunks per y-row)
    for (int idx = tid; idx < XSZ*8; idx += 128) {
        int y = idx >> 3, kxl = idx & 7;
        int kx = kx0 + kxl; if (kx > 128) kx = 128;
        long g = (long)((b << 8) + y) * HSPEC + kx;
        tin[y][kxl]   = g_spec[g];
        ctile[y][kxl] = ctf[g];
    }
    __syncthreads();
    float2 v[16];
    #pragma unroll
    for (int n2 = 0; n2 < 16; n2++) v[n2] = tin[t + (n2 << 4)][f];
    fft256_shfl<false>(v, t, stw);
    // X[ky = t+16j] sits at v[SLOT(j)] -> permute in place, then ctf multiply
    slot_permute(v);                      // v[j] = X[t + 16 j]
    #pragma unroll
    for (int j = 0; j < 16; j++) {
        float c = ctile[t + (j << 4)][f];
        v[j].x *= c; v[j].y *= c;
    }
    // inverse needs input z[t + 16 n] at v[n] — already in place
    fft256_shfl<true>(v, t, stw);
    // each thread writes back exactly the tin entries it read — no hazard
    #pragma unroll
    for (int m = 0; m < 16; m++) tin[t + (m << 4)][f] = v[SLOT(m)];
    __syncthreads();
    // coalesced write-back to [b][y][k]
    for (int idx = tid; idx < XSZ*8; idx += 128) {
        int y = idx >> 3, kxl = idx & 7;
        int kx = kx0 + kxl;
        if (kx <= 128)
            g_spec[(long)((b << 8) + y) * HSPEC + kx] = tin[y][kxl];
    }
}

// two-for-one inverse row rFFT ([b][y][k] reads coalesced).
// irfft drops Im(h[0]) and Im(h[128]) — zero them before the packed merge.
__global__ void ifftrow_kernel(float* __restrict__ out) {
    __shared__ float RA[4][264], IA[4][264], RB[4][264], IB[4][264];
    __shared__ float2 tw[64];
    int tid = threadIdx.x, sub = tid >> 6, lane = tid & 63;
    if (tid < 64) tw[tid] = g_tw[tid];
    int rp = blockIdx.x * 4 + sub;
    int b  = rp >> 7;
    int y0 = (rp & 127) << 1;
    int y1 = y0 + 1;
    long base0 = (long)((b << 8) | y0) * HSPEC;
    long base1 = (long)((b << 8) | y1) * HSPEC;
    for (int k = lane; k <= 128; k += 64) {
        float2 A  = g_spec[base0 + k];
        float2 Bv = g_spec[base1 + k];
        if (k == 0 || k == 128) { A.y = 0.f; Bv.y = 0.f; }   // irfft semantics
        RA[sub][SKEW(k)] = A.x - Bv.y;     // z[k] = Fa[k] + i*Fb[k]
        IA[sub][SKEW(k)] = A.y + Bv.x;
        if (k >= 1 && k <= 127) {
            int m = 256 - k;               // z[m] = conj(Fa[k]) + i*conj(Fb[k])
            RA[sub][SKEW(m)] =  A.x + Bv.y;
            IA[sub][SKEW(m)] = -A.y + Bv.x;
        }
    }
    __syncthreads();
    fft_r4<true>(RA[sub], IA[sub], RB[sub], IB[sub], tw, lane);
    const float sc = 1.0f / 65536.0f;
    float* o0 = out + ((long)((b << 8) | y0) << 8);
    float* o1 = out + ((long)((b << 8) | y1) << 8);
    for (int i = lane; i < XSZ; i += 64) {
        o0[i] = RA[sub][SKEW(i)] * sc;
        o1[i] = IA[sub][SKEW(i)] * sc;
    }
}

// ---------------- launch -----------------------------------------------------

extern "C" void kernel_launch(void* const* d_in, const int* in_sizes, int n_in,
                              void* d_out, int out_size) {
    const float* rows   = (const float*)d_in[0];
    const float* shifts = (const float*)d_in[1];
    const float* latent = (const float*)d_in[2];
    const float* coords = (const float*)d_in[3];
    const float* values = (const float*)d_in[4];
    const float* W0 = (const float*)d_in[5];
    const float* b0 = (const float*)d_in[6];
    const float* W1 = (const float*)d_in[7];
    const float* b1 = (const float*)d_in[8];
    const float* W2 = (const float*)d_in[9];
    const float* b2 = (const float*)d_in[10];
    const float* W3 = (const float*)d_in[11];
    const float* b3 = (const float*)d_in[12];
    const float* Wd = (const float*)d_in[13];
    const float* bd = (const float*)d_in[14];
    const float* ctf = (const float*)d_in[15];
    float* out = (float*)d_out;

    zero_prep_kernel<<<IMG_ELEMS/4/256, 256>>>(rows, shifts, latent,
                                               W0, b0, W1, b1, W2, b2, W3, b3);
    scatter_kernel<<<(NPTS + 255)/256, 256>>>(coords, values, Wd, bd);
    fftrow_kernel<<<BB*XSZ/2/4, 256>>>();
    fftcol_kernel<<<BB*17, 128>>>(ctf);
    ifftrow_kernel<<<BB*XSZ/2/4, 256>>>(out);
}

// round 14
// speedup vs baseline: 1.0591x; 1.0591x over previous
#include <cuda_runtime.h>
#include <math.h>

#define BB 16
#define LATD 8
#define NPTS 500000
#define XSZ 256
#define HSPEC 129   // XSZ/2 + 1
#define IMG_ELEMS (BB*XSZ*XSZ)

// ---------------- scratch (device globals; no allocation allowed) ----------
__device__ float  g_img[IMG_ELEMS];                  // 4 MB accumulation image
__device__ float2 g_spec[BB*XSZ*HSPEC];              // spectrum, layout [b][y][k]
__device__ float  g_params[BB][16];                  // R rows(6), shifts(2), h(8)
__device__ float2 g_tw[128];                         // exp(-2*pi*i*k/256)

// Gaussian kernel (sigma=1, radius=3), normalized (double-derived constants)
__device__ __constant__ float c_gk[7] = {
    0.0044330481f, 0.0540055826f, 0.2420362294f, 0.3990502730f,
    0.2420362294f, 0.0540055826f, 0.0044330481f
};

#define SKEW(i) ((i) + ((i) >> 5))   // bank-conflict skew for SoA smem

// ---------------- zero + prep (merged) --------------------------------------

__global__ void zero_prep_kernel(const float* __restrict__ rows,
                                 const float* __restrict__ shifts,
                                 const float* __restrict__ latent,
                                 const float* __restrict__ W0, const float* __restrict__ b0,
                                 const float* __restrict__ W1, const float* __restrict__ b1,
                                 const float* __restrict__ W2, const float* __restrict__ b2,
                                 const float* __restrict__ W3, const float* __restrict__ b3) {
    int i = blockIdx.x * blockDim.x + threadIdx.x;
    ((float4*)g_img)[i] = make_float4(0.f, 0.f, 0.f, 0.f);
    if (blockIdx.x != 0) return;
    int tid = threadIdx.x;
    if (tid < 128) {
        double s, c;
        sincos(-3.14159265358979323846 * (double)tid / 128.0, &s, &c);
        g_tw[tid] = make_float2((float)c, (float)s);
    }
    int b = tid;
    if (b >= BB) return;
    // ---- FROZEN position-path arithmetic (do not modify) ----
    float rot  = rows[b*3+0];
    float tilt = rows[b*3+1];
    float psi  = rows[b*3+2];
    float ca = cosf(rot),  sa = sinf(rot);
    float cb = cosf(tilt), sb = sinf(tilt);
    float cg = cosf(psi),  sg = sinf(psi);
    float cgcb = __fmul_rn(cg, cb);
    float sgcb = __fmul_rn(sg, cb);
    g_params[b][0] = __fsub_rn(__fmul_rn(cgcb, ca), __fmul_rn(sg, sa));
    g_params[b][1] = __fadd_rn(__fmul_rn(cgcb, sa), __fmul_rn(sg, ca));
    g_params[b][2] = -__fmul_rn(cg, sb);
    g_params[b][3] = __fsub_rn(__fmul_rn(-sgcb, ca), __fmul_rn(cg, sa));
    g_params[b][4] = __fadd_rn(__fmul_rn(-sgcb, sa), __fmul_rn(cg, ca));
    g_params[b][5] = __fmul_rn(sg, sb);
    g_params[b][6] = shifts[b*2+0];
    g_params[b][7] = shifts[b*2+1];

    float h[LATD];
    #pragma unroll
    for (int j = 0; j < LATD; j++) {
        float z = b0[j];
        #pragma unroll
        for (int l = 0; l < LATD; l++) z += latent[b*LATD+l] * W0[l*LATD+j];
        h[j] = sinf(30.0f * z);
    }
    const float* Ws[3] = {W1, W2, W3};
    const float* bs[3] = {b1, b2, b3};
    for (int L = 0; L < 3; L++) {
        float t[LATD];
        #pragma unroll
        for (int j = 0; j < LATD; j++) {
            float z = bs[L][j];
            #pragma unroll
            for (int l = 0; l < LATD; l++) z += h[l] * Ws[L][l*LATD+j];
            t[j] = sinf(z);
        }
        #pragma unroll
        for (int j = 0; j < LATD; j++) h[j] += t[j];
    }
    #pragma unroll
    for (int j = 0; j < LATD; j++) g_params[b][8+j] = h[j];
}

// ---------------- scatter ----------------------------------------------------

__global__ void scatter_kernel(const float* __restrict__ coords,
                               const float* __restrict__ values,
                               const float* __restrict__ Wd,
                               const float* __restrict__ bd) {
    __shared__ float sp[BB][16];
    __shared__ float sc[768];
    int t = threadIdx.x;
    if (t < BB*16) ((float*)sp)[t] = ((const float*)g_params)[t];
    int base = blockIdx.x * 256 * 3;
    #pragma unroll
    for (int f = 0; f < 3; f++) {
        int g = base + t + f*256;
        sc[t + f*256] = (g < NPTS*3) ? coords[g] : 0.0f;
    }
    __syncthreads();

    int n = blockIdx.x * blockDim.x + t;
    if (n >= NPTS) return;

    float cx = sc[t*3+0];
    float cy = sc[t*3+1];
    float cz = sc[t*3+2];
    float v   = values[n];
    float bdn = bd[n];
    float wd[LATD];
    #pragma unroll
    for (int l = 0; l < LATD; l++) wd[l] = Wd[l*NPTS + n];

    #pragma unroll
    for (int b = 0; b < BB; b++) {
        // ---- FROZEN position-path arithmetic (do not modify) ----
        float x = __fmul_rn(sp[b][0], cx);
        x = __fmaf_rn(sp[b][1], cy, x);
        x = __fmaf_rn(sp[b][2], cz, x);
        float y = __fmul_rn(sp[b][3], cx);
        y = __fmaf_rn(sp[b][4], cy, y);
        y = __fmaf_rn(sp[b][5], cz, y);
        float fx = rintf(__fadd_rn(__fadd_rn(x, sp[b][6]), 128.0f));
        float fy = rintf(__fadd_rn(__fadd_rn(y, sp[b][7]), 128.0f));
        fx = fminf(fmaxf(fx, 0.0f), 255.0f);
        fy = fminf(fmaxf(fy, 0.0f), 255.0f);
        int ix = (int)fx;
        int iy = (int)fy;
        float dot = sp[b][8] * wd[0];
        #pragma unroll
        for (int l = 1; l < LATD; l++) dot += sp[b][8+l] * wd[l];
        float val = v + (dot + bdn);
        atomicAdd(&g_img[(b << 16) | (iy << 8) | ix], val);
    }
}

// ---- radix-4 Stockham FFT, N=256, 64 lanes per FFT, SoA smem + skew --------

template<bool INV>
__device__ __forceinline__ void fft_r4(float* RA, float* IA, float* RB, float* IB,
                                       const float2* tw, int lane) {
    float* sr = RA; float* si = IA; float* dr = RB; float* di = IB;
    #pragma unroll
    for (int st = 0; st < 4; st++) {
        const int Ns = 1 << (2*st);
        int k    = lane & (Ns - 1);
        int base = ((lane - k) << 2) + k;
        float2 w1 = tw[k << (6 - 2*st)];
        if (INV) w1.y = -w1.y;
        float w2r = w1.x*w1.x - w1.y*w1.y, w2i = 2.f*w1.x*w1.y;
        float w3r = w2r*w1.x - w2i*w1.y,  w3i = w2r*w1.y + w2i*w1.x;
        float ar  = sr[SKEW(lane)],       ai  = si[SKEW(lane)];
        float br_ = sr[SKEW(lane+64)],    bi  = si[SKEW(lane+64)];
        float cr  = sr[SKEW(lane+128)],   ci  = si[SKEW(lane+128)];
        float dr_ = sr[SKEW(lane+192)],   di_ = si[SKEW(lane+192)];
        float tbr = w1.x*br_ - w1.y*bi,   tbi = w1.x*bi  + w1.y*br_;
        float tcr = w2r*cr  - w2i*ci,     tci = w2r*ci  + w2i*cr;
        float tdr = w3r*dr_ - w3i*di_,    tdi = w3r*di_ + w3i*dr_;
        float t0r = ar + tcr,  t0i = ai + tci;
        float t1r = ar - tcr,  t1i = ai - tci;
        float t2r = tbr + tdr, t2i = tbi + tdi;
        float t3r = tbr - tdr, t3i = tbi - tdi;
        dr[SKEW(base)]      = t0r + t2r;  di[SKEW(base)]      = t0i + t2i;
        dr[SKEW(base+2*Ns)] = t0r - t2r;  di[SKEW(base+2*Ns)] = t0i - t2i;
        if (!INV) {
            dr[SKEW(base+Ns)]   = t1r + t3i;  di[SKEW(base+Ns)]   = t1i - t3r;
            dr[SKEW(base+3*Ns)] = t1r - t3i;  di[SKEW(base+3*Ns)] = t1i + t3r;
        } else {
            dr[SKEW(base+Ns)]   = t1r - t3i;  di[SKEW(base+Ns)]   = t1i + t3r;
            dr[SKEW(base+3*Ns)] = t1r + t3i;  di[SKEW(base+3*Ns)] = t1i - t3r;
        }
        __syncthreads();
        float* tp;
        tp = sr; sr = dr; dr = tp;
        tp = si; si = di; di = tp;
    }
}

// fused y-blur + x-blur + two-for-one forward row rFFT (measured 12.0us).
// Block: 256 threads = 4 FFTs = 4 row pairs; grid 512. Writes [b][y][k].
__global__ void fftrow_kernel() {
    __shared__ float RA[4][264], IA[4][264], RB[4][264], IB[4][264];
    __shared__ float2 tw[64];
    int tid = threadIdx.x, sub = tid >> 6, lane = tid & 63;
    if (tid < 64) tw[tid] = g_tw[tid];
    int rp = blockIdx.x * 4 + sub;        // pair index, 128 pairs per image
    int b  = rp >> 7;
    int y0 = (rp & 127) << 1;
    int y1 = y0 + 1;
    const float* imgb = g_img + (b << 16);
    for (int i = lane; i < XSZ; i += 64) {
        float a0 = 0.f, a1 = 0.f;
        #pragma unroll
        for (int d = -3; d <= 3; d++) {
            int ya = y0 + d;
            if (ya >= 0 && ya < XSZ) a0 += c_gk[d+3] * imgb[(ya << 8) + i];
            int yb = y1 + d;
            if (yb >= 0 && yb < XSZ) a1 += c_gk[d+3] * imgb[(yb << 8) + i];
        }
        RB[sub][i] = a0;
        IB[sub][i] = a1;
    }
    __syncthreads();
    for (int i = lane; i < XSZ; i += 64) {
        float a0 = 0.f, a1 = 0.f;
        #pragma unroll
        for (int d = -3; d <= 3; d++) {
            int xx = i + d;
            if (xx >= 0 && xx < XSZ) {
                a0 += c_gk[d+3] * RB[sub][xx];
                a1 += c_gk[d+3] * IB[sub][xx];
            }
        }
        RA[sub][SKEW(i)] = a0;
        IA[sub][SKEW(i)] = a1;
    }
    __syncthreads();
    fft_r4<false>(RA[sub], IA[sub], RB[sub], IB[sub], tw, lane);
    long base0 = (long)((b << 8) | y0) * HSPEC;
    long base1 = (long)((b << 8) | y1) * HSPEC;
    for (int k = lane; k <= 128; k += 64) {
        int kn = (256 - k) & 255;
        float zr = RA[sub][SKEW(k)],  zi = IA[sub][SKEW(k)];
        float nr = RA[sub][SKEW(kn)], ni = IA[sub][SKEW(kn)];
        g_spec[base0 + k] = make_float2(0.5f*(zr + nr), 0.5f*(zi - ni));
        g_spec[base1 + k] = make_float2(0.5f*(zi + ni), 0.5f*(nr - zr));
    }
}

// forward y FFT, ctf multiply, inverse y FFT — radix-4 smem FFT, 64 lanes
// per FFT -> 132k threads (~28 warps/SM) to hide L2 latency on the strided
// [b][y][k] column accesses. Block: 256 threads = 4 kx columns; grid BB*33.
__global__ void fftcol_kernel(const float* __restrict__ ctf) {
    __shared__ float RA[4][264], IA[4][264], RB[4][264], IB[4][264];
    __shared__ float2 tw[64];
    int tid = threadIdx.x, sub = tid >> 6, lane = tid & 63;
    if (tid < 64) tw[tid] = g_tw[tid];
    int b  = blockIdx.x / 33;
    int kx = (blockIdx.x % 33) * 4 + sub;
    bool act = (kx <= 128);
    int kxe = act ? kx : 128;
    long base = (long)(b << 8) * HSPEC + kxe;
    for (int y = lane; y < XSZ; y += 64) {
        float2 v = g_spec[base + (long)y * HSPEC];
        RA[sub][SKEW(y)] = v.x;
        IA[sub][SKEW(y)] = v.y;
    }
    __syncthreads();
    fft_r4<false>(RA[sub], IA[sub], RB[sub], IB[sub], tw, lane);
    for (int ky = lane; ky < XSZ; ky += 64) {
        float c = ctf[base + (long)ky * HSPEC];
        RA[sub][SKEW(ky)] *= c;
        IA[sub][SKEW(ky)] *= c;
    }
    __syncthreads();
    fft_r4<true>(RA[sub], IA[sub], RB[sub], IB[sub], tw, lane);
    if (act) {
        for (int y = lane; y < XSZ; y += 64)
            g_spec[base + (long)y * HSPEC] =
                make_float2(RA[sub][SKEW(y)], IA[sub][SKEW(y)]);
    }
}

// two-for-one inverse row rFFT ([b][y][k] reads coalesced).
// irfft drops Im(h[0]) and Im(h[128]) — zero them before the packed merge.
__global__ void ifftrow_kernel(float* __restrict__ out) {
    __shared__ float RA[4][264], IA[4][264], RB[4][264], IB[4][264];
    __shared__ float2 tw[64];
    int tid = threadIdx.x, sub = tid >> 6, lane = tid & 63;
    if (tid < 64) tw[tid] = g_tw[tid];
    int rp = blockIdx.x * 4 + sub;
    int b  = rp >> 7;
    int y0 = (rp & 127) << 1;
    int y1 = y0 + 1;
    long base0 = (long)((b << 8) | y0) * HSPEC;
    long base1 = (long)((b << 8) | y1) * HSPEC;
    for (int k = lane; k <= 128; k += 64) {
        float2 A  = g_spec[base0 + k];
        float2 Bv = g_spec[base1 + k];
        if (k == 0 || k == 128) { A.y = 0.f; Bv.y = 0.f; }   // irfft semantics
        RA[sub][SKEW(k)] = A.x - Bv.y;     // z[k] = Fa[k] + i*Fb[k]
        IA[sub][SKEW(k)] = A.y + Bv.x;
        if (k >= 1 && k <= 127) {
            int m = 256 - k;               // z[m] = conj(Fa[k]) + i*conj(Fb[k])
            RA[sub][SKEW(m)] =  A.x + Bv.y;
            IA[sub][SKEW(m)] = -A.y + Bv.x;
        }
    }
    __syncthreads();
    fft_r4<true>(RA[sub], IA[sub], RB[sub], IB[sub], tw, lane);
    const float sc = 1.0f / 65536.0f;
    float* o0 = out + ((long)((b << 8) | y0) << 8);
    float* o1 = out + ((long)((b << 8) | y1) << 8);
    for (int i = lane; i < XSZ; i += 64) {
        o0[i] = RA[sub][SKEW(i)] * sc;
        o1[i] = IA[sub][SKEW(i)] * sc;
    }
}

// ---------------- launch -----------------------------------------------------

extern "C" void kernel_launch(void* const* d_in, const int* in_sizes, int n_in,
                              void* d_out, int out_size) {
    const float* rows   = (const float*)d_in[0];
    const float* shifts = (const float*)d_in[1];
    const float* latent = (const float*)d_in[2];
    const float* coords = (const float*)d_in[3];
    const float* values = (const float*)d_in[4];
    const float* W0 = (const float*)d_in[5];
    const float* b0 = (const float*)d_in[6];
    const float* W1 = (const float*)d_in[7];
    const float* b1 = (const float*)d_in[8];
    const float* W2 = (const float*)d_in[9];
    const float* b2 = (const float*)d_in[10];
    const float* W3 = (const float*)d_in[11];
    const float* b3 = (const float*)d_in[12];
    const float* Wd = (const float*)d_in[13];
    const float* bd = (const float*)d_in[14];
    const float* ctf = (const float*)d_in[15];
    float* out = (float*)d_out;

    zero_prep_kernel<<<IMG_ELEMS/4/256, 256>>>(rows, shifts, latent,
                                               W0, b0, W1, b1, W2, b2, W3, b3);
    scatter_kernel<<<(NPTS + 255)/256, 256>>>(coords, values, Wd, bd);
    fftrow_kernel<<<BB*XSZ/2/4, 256>>>();
    fftcol_kernel<<<BB*33, 256>>>(ctf);
    ifftrow_kernel<<<BB*XSZ/2/4, 256>>>(out);
}